// round 7
// baseline (speedup 1.0000x reference)
#include <cuda_runtime.h>
#include <cuda_bf16.h>
#include <cstdint>

#define DIM   256
#define HIST  200
#define VROWS 100000
#define EPSF  1e-12f
#define ROWB  528            // smem row stride bytes: (256+8) bf16

// ---------------- persistent device scratch ----------------
__device__ __nv_bfloat16 g_Bt[DIM * DIM];           // W1^T  (Bt[n][k] = W1[k][n])
__device__ float         g_C[HIST * DIM];           // P@W2 + bias
__device__ uint32_t      g_TV[(size_t)VROWS * DIM]; // packed: lo16=T bf16, hi16=vnorm bf16

// ---------------- helpers ----------------
__device__ __forceinline__ uint32_t smem_u32(const void* p) {
    uint32_t a;
    asm("{ .reg .u64 t; cvta.to.shared.u64 t, %1; cvt.u32.u64 %0, t; }" : "=r"(a) : "l"(p));
    return a;
}
__device__ __forceinline__ float tanh_fast(float x) {
    float y; asm("tanh.approx.f32 %0, %1;" : "=f"(y) : "f"(x)); return y;
}
__device__ __forceinline__ unsigned long long pk2(float lo, float hi) {
    unsigned long long r; asm("mov.b64 %0, {%1,%2};" : "=l"(r) : "f"(lo), "f"(hi)); return r;
}
__device__ __forceinline__ void upk2(unsigned long long v, float& lo, float& hi) {
    asm("mov.b64 {%0,%1}, %2;" : "=f"(lo), "=f"(hi) : "l"(v));
}
__device__ __forceinline__ unsigned long long add2(unsigned long long a, unsigned long long b) {
    unsigned long long r; asm("add.rn.f32x2 %0, %1, %2;" : "=l"(r) : "l"(a), "l"(b)); return r;
}
__device__ __forceinline__ unsigned long long fma2(unsigned long long a, unsigned long long b,
                                                   unsigned long long c) {
    unsigned long long r; asm("fma.rn.f32x2 %0, %1, %2, %3;" : "=l"(r) : "l"(a), "l"(b), "l"(c));
    return r;
}
__device__ __forceinline__ void ldsm_x4(uint32_t* r, uint32_t addr) {
    asm volatile("ldmatrix.sync.aligned.m8n8.x4.shared.b16 {%0,%1,%2,%3}, [%4];"
                 : "=r"(r[0]), "=r"(r[1]), "=r"(r[2]), "=r"(r[3]) : "r"(addr));
}
__device__ __forceinline__ void mma_bf16(float* d, const uint32_t* a,
                                         uint32_t b0, uint32_t b1) {
    asm volatile(
        "mma.sync.aligned.m16n8k16.row.col.f32.bf16.bf16.f32 "
        "{%0,%1,%2,%3}, {%4,%5,%6,%7}, {%8,%9}, {%0,%1,%2,%3};"
        : "+f"(d[0]), "+f"(d[1]), "+f"(d[2]), "+f"(d[3])
        : "r"(a[0]), "r"(a[1]), "r"(a[2]), "r"(a[3]), "r"(b0), "r"(b1));
}
__device__ __forceinline__ void cp16(uint32_t dst, const void* src) {
    asm volatile("cp.async.cg.shared.global [%0], [%1], 16;" :: "r"(dst), "l"(src));
}
__device__ __forceinline__ void cp_commit() { asm volatile("cp.async.commit_group;" ::: "memory"); }
__device__ __forceinline__ void cp_wait0()  { asm volatile("cp.async.wait_group 0;" ::: "memory"); }

// ---------------- small precompute kernels ----------------
__global__ void build_Bt_kernel(const float* __restrict__ W1) {
    const int n = blockIdx.x, k = threadIdx.x;
    g_Bt[n * DIM + k] = __float2bfloat16(W1[k * DIM + n]);
}

__global__ void compute_C_kernel(const float* __restrict__ P,
                                 const float* __restrict__ W2,
                                 const float* __restrict__ bias) {
    __shared__ float sP[DIM];
    const int h = blockIdx.x, d = threadIdx.x;
    sP[d] = P[h * DIM + d];
    __syncthreads();
    float acc = 0.f;
    #pragma unroll 16
    for (int k = 0; k < DIM; ++k) acc = fmaf(sP[k], W2[k * DIM + d], acc);
    g_C[h * DIM + d] = acc + bias[h * DIM + d];
}

// ---------------- TV = pack(max_norm(venue) @ W1, max_norm(venue)) ----------------
// 64-row tiles, 256 threads, smem A 33792 + B 33792 = 67584 -> occ 3
#define GSM_A 0
#define GSM_B 33792
#define GSM_BYTES 67584

__global__ __launch_bounds__(256, 3)
void gemm_T_kernel(const float* __restrict__ venue, int rows) {
    extern __shared__ __align__(16) char sm[];
    const int tid = threadIdx.x, lane = tid & 31, warp = tid >> 5;
    const int M0 = blockIdx.x * 64;
    const uint32_t smA = smem_u32(sm + GSM_A);
    const uint32_t smB = smem_u32(sm + GSM_B);

    // ---- issue B chunk 0 copy (overlaps normalize) ----
    {
        const char* src = reinterpret_cast<const char*>(g_Bt);
        #pragma unroll
        for (int s = 0; s < 8; ++s) {
            const int i = tid + s * 256;            // 0..2047
            const int row = i >> 5, j = i & 31;
            cp16(smB + row * ROWB + j * 16, src + row * 512 + j * 16);
        }
        cp_commit();
    }

    // ---- normalize 64 venue rows -> bf16 -> smem A ----
    #pragma unroll
    for (int i = 0; i < 8; ++i) {
        const int lr  = warp * 8 + i;
        const int row = M0 + lr;
        if (row < rows) {
            const float4* src = reinterpret_cast<const float4*>(venue + (size_t)row * DIM) + lane * 2;
            float4 x0 = src[0], x1 = src[1];
            float ss = x0.x*x0.x + x0.y*x0.y + x0.z*x0.z + x0.w*x0.w
                     + x1.x*x1.x + x1.y*x1.y + x1.z*x1.z + x1.w*x1.w;
            #pragma unroll
            for (int o = 16; o > 0; o >>= 1) ss += __shfl_xor_sync(0xffffffffu, ss, o);
            const float sc = fminf(1.0f, 1.0f / fmaxf(sqrtf(ss), EPSF));   // torch max_norm=1
            __nv_bfloat162 b0 = __floats2bfloat162_rn(x0.x*sc, x0.y*sc);
            __nv_bfloat162 b1 = __floats2bfloat162_rn(x0.z*sc, x0.w*sc);
            __nv_bfloat162 b2 = __floats2bfloat162_rn(x1.x*sc, x1.y*sc);
            __nv_bfloat162 b3 = __floats2bfloat162_rn(x1.z*sc, x1.w*sc);
            uint4 o4;
            o4.x = *reinterpret_cast<uint32_t*>(&b0); o4.y = *reinterpret_cast<uint32_t*>(&b1);
            o4.z = *reinterpret_cast<uint32_t*>(&b2); o4.w = *reinterpret_cast<uint32_t*>(&b3);
            *reinterpret_cast<uint4*>(sm + GSM_A + lr * ROWB + lane * 16) = o4;
        } else {
            *reinterpret_cast<uint4*>(sm + GSM_A + lr * ROWB + lane * 16) = make_uint4(0,0,0,0);
        }
    }

    // warp tile 32x16: mgrp = warp>>2 (row half), ngrp = warp&3 (16-col group)
    const int qr = lane >> 2, qc = lane & 3;
    const int mgrp = warp >> 2, ngrp = warp & 3;
    const uint32_t aAddr = smA + (uint32_t)((mgrp * 32 + (lane & 15)) * ROWB + (lane >> 4) * 16);
    const uint32_t bAddr = smB + (uint32_t)((ngrp * 16 + (lane & 7) + ((lane >> 4) & 1) * 8) * ROWB
                                            + ((lane >> 3) & 1) * 16);

    #pragma unroll 1
    for (int chunk = 0; chunk < 4; ++chunk) {
        cp_wait0();
        __syncthreads();       // B chunk resident; A staged

        float acc[2][2][4];
        #pragma unroll
        for (int mt = 0; mt < 2; ++mt)
            #pragma unroll
            for (int nt = 0; nt < 2; ++nt)
                #pragma unroll
                for (int i = 0; i < 4; ++i) acc[mt][nt][i] = 0.f;

        #pragma unroll 4
        for (int ks = 0; ks < 16; ++ks) {
            uint32_t af[2][4], bf[4];
            ldsm_x4(af[0], aAddr + ks * 32);
            ldsm_x4(af[1], aAddr + 16 * ROWB + ks * 32);
            ldsm_x4(bf, bAddr + ks * 32);
            #pragma unroll
            for (int mt = 0; mt < 2; ++mt)
                #pragma unroll
                for (int nt = 0; nt < 2; ++nt)
                    mma_bf16(acc[mt][nt], af[mt], bf[nt * 2], bf[nt * 2 + 1]);
        }
        __syncthreads();       // all warps done with B before refill

        if (chunk < 3) {
            const char* src = reinterpret_cast<const char*>(g_Bt + (chunk + 1) * 64 * DIM);
            #pragma unroll
            for (int s = 0; s < 8; ++s) {
                const int i = tid + s * 256;
                const int row = i >> 5, j = i & 31;
                cp16(smB + row * ROWB + j * 16, src + row * 512 + j * 16);
            }
            cp_commit();
        }

        // ---- pack T(bf16) + vnorm(bf16) -> g_TV (uint32/elem); overlaps B refill ----
        #pragma unroll
        for (int mt = 0; mt < 2; ++mt) {
            const int lr0 = mgrp * 32 + mt * 16 + qr;
            #pragma unroll
            for (int nt = 0; nt < 2; ++nt) {
                const int col = chunk * 64 + ngrp * 16 + nt * 8 + 2 * qc;
                #pragma unroll
                for (int half = 0; half < 2; ++half) {
                    const int r0 = M0 + lr0 + half * 8;
                    if (r0 < rows) {
                        const uint32_t hh = *reinterpret_cast<const uint32_t*>(
                            sm + GSM_A + (lr0 + half * 8) * ROWB + col * 2);
                        __nv_bfloat162 tp = __floats2bfloat162_rn(
                            acc[mt][nt][half * 2 + 0], acc[mt][nt][half * 2 + 1]);
                        const uint32_t tpu = *reinterpret_cast<uint32_t*>(&tp);
                        uint2 st;
                        st.x = __byte_perm(tpu, hh, 0x5410);   // {T_lo, v_lo}
                        st.y = __byte_perm(tpu, hh, 0x7632);   // {T_hi, v_hi}
                        *reinterpret_cast<uint2*>(g_TV + (size_t)r0 * DIM + col) = st;
                    }
                }
            }
        }
    }
}

// ---------------- main kernel: 2 batch items per CTA, col-pair per thread ----------------
// e^t on [-1,1]: Chebyshev-derived degree-6 poly, abs err ~3.4e-6
#define EC0 0.999999801335f
#define EC1 1.000022289990f
#define EC2 0.500006347345f
#define EC3 0.166488873156f
#define EC4 0.041635012000f
#define EC5 0.008686820990f
#define EC6 0.001439274330f

__global__ __launch_bounds__(256)
void geo_main_kernel(const int* __restrict__ batch_u,
                     const int* __restrict__ batch_v,
                     const int* __restrict__ batch_history,
                     const float* __restrict__ user_emb,
                     const float* __restrict__ venue_emb,
                     const float* __restrict__ a_ptr,
                     float* __restrict__ out) {
    __shared__ int   sidx[2 * HIST];
    __shared__ float sredA[8], sredB[8], sredC[8], sredD[8];
    __shared__ float sbc[2][3];

    const int bx = blockIdx.x, tid = threadIdx.x, lane = tid & 31, warp = tid >> 5;
    const int bloc = warp >> 2;               // 0 or 1: which batch item
    const int b = bx * 2 + bloc;
    const int wg = tid & 127;                 // 0..127
    const int d0 = wg * 2;                    // column pair

    #pragma unroll
    for (int i = tid; i < 2 * HIST; i += 256) sidx[i] = batch_history[bx * 2 * HIST + i];
    __syncthreads();

    const unsigned long long K6 = pk2(EC6, EC6), K5 = pk2(EC5, EC5), K4 = pk2(EC4, EC4),
                             K3 = pk2(EC3, EC3), K2 = pk2(EC2, EC2), K1 = pk2(EC1, EC1),
                             K0 = pk2(EC0, EC0);
    unsigned long long den2 = 0ull, num2 = 0ull;   // f32x2 {0,0}
    const int* sI = sidx + bloc * HIST;

    #pragma unroll 2
    for (int r = 0; r < HIST; ++r) {
        const uint32_t off = ((uint32_t)sI[r] << 8) + d0;
        const uint2 tv  = __ldg(reinterpret_cast<const uint2*>(g_TV + off));
        const float2 cc = __ldg(reinterpret_cast<const float2*>(g_C + r * DIM + d0));
        const float t0 = __uint_as_float(tv.x << 16);
        const float t1 = __uint_as_float(tv.y << 16);
        const float h0 = __uint_as_float(tv.x & 0xffff0000u);
        const float h1 = __uint_as_float(tv.y & 0xffff0000u);
        const float w0 = tanh_fast(t0 + cc.x);
        const float w1 = tanh_fast(t1 + cc.y);
        const unsigned long long w2 = pk2(w0, w1);
        unsigned long long e2 = fma2(K6, w2, K5);
        e2 = fma2(e2, w2, K4);
        e2 = fma2(e2, w2, K3);
        e2 = fma2(e2, w2, K2);
        e2 = fma2(e2, w2, K1);
        e2 = fma2(e2, w2, K0);
        den2 = add2(den2, e2);
        num2 = fma2(e2, pk2(h0, h1), num2);
    }

    float dn0, dn1, nm0, nm1;
    upk2(den2, dn0, dn1);
    upk2(num2, nm0, nm1);

    // ---- l = num/den + a; score = || l2n(u) + l2n(l) - l2n(v) || ----
    const float a_val = a_ptr[0];
    const float lv0 = nm0 / dn0 + a_val;
    const float lv1 = nm1 / dn1 + a_val;
    const float2 uv = __ldg(reinterpret_cast<const float2*>(
        user_emb + (size_t)batch_u[b] * DIM + d0));
    const float2 vv = __ldg(reinterpret_cast<const float2*>(
        venue_emb + (size_t)batch_v[b] * DIM + d0));
    float su = uv.x*uv.x + uv.y*uv.y;
    float sv = vv.x*vv.x + vv.y*vv.y;
    float sl = lv0*lv0 + lv1*lv1;
    #pragma unroll
    for (int o = 16; o > 0; o >>= 1) {
        su += __shfl_xor_sync(0xffffffffu, su, o);
        sv += __shfl_xor_sync(0xffffffffu, sv, o);
        sl += __shfl_xor_sync(0xffffffffu, sl, o);
    }
    if (lane == 0) { sredA[warp] = su; sredB[warp] = sv; sredC[warp] = sl; }
    __syncthreads();
    if (wg == 0) {   // tid 0 and tid 128: one leader per batch item
        float tu = 0.f, tv2 = 0.f, tl = 0.f;
        #pragma unroll
        for (int w = 0; w < 4; ++w) {
            tu  += sredA[bloc * 4 + w];
            tv2 += sredB[bloc * 4 + w];
            tl  += sredC[bloc * 4 + w];
        }
        sbc[bloc][0] = 1.f / fmaxf(sqrtf(tu), EPSF);
        sbc[bloc][1] = 1.f / fmaxf(sqrtf(tv2), EPSF);
        sbc[bloc][2] = 1.f / fmaxf(sqrtf(tl), EPSF);
    }
    __syncthreads();
    const float ibu = sbc[bloc][0], ibv = sbc[bloc][1], ibl = sbc[bloc][2];
    const float s0 = uv.x * ibu + lv0 * ibl - vv.x * ibv;
    const float s1 = uv.y * ibu + lv1 * ibl - vv.y * ibv;
    float ssq = s0 * s0 + s1 * s1;
    #pragma unroll
    for (int o = 16; o > 0; o >>= 1) ssq += __shfl_xor_sync(0xffffffffu, ssq, o);
    if (lane == 0) sredD[warp] = ssq;
    __syncthreads();
    if (wg == 0) {
        float tot = 0.f;
        #pragma unroll
        for (int w = 0; w < 4; ++w) tot += sredD[bloc * 4 + w];
        out[b] = sqrtf(tot);
    }
}

// ---------------- harness entry ----------------
extern "C" void kernel_launch(void* const* d_in, const int* in_sizes, int n_in,
                              void* d_out, int out_size) {
    const int*   batch_u       = (const int*)d_in[0];
    const int*   batch_v       = (const int*)d_in[1];
    const int*   batch_history = (const int*)d_in[2];
    const float* user_emb      = (const float*)d_in[5];
    const float* venue_emb     = (const float*)d_in[6];
    const float* W1            = (const float*)d_in[7];
    const float* W2            = (const float*)d_in[8];
    const float* P             = (const float*)d_in[9];
    const float* bias          = (const float*)d_in[10];
    const float* a             = (const float*)d_in[11];
    float* out = (float*)d_out;

    const int B = in_sizes[0];
    int rows = in_sizes[6] / DIM;
    if (rows > VROWS) rows = VROWS;

    cudaFuncSetAttribute(gemm_T_kernel,
                         cudaFuncAttributeMaxDynamicSharedMemorySize, GSM_BYTES);

    build_Bt_kernel<<<DIM, DIM>>>(W1);
    compute_C_kernel<<<HIST, DIM>>>(P, W2, bias);
    gemm_T_kernel<<<(rows + 63) / 64, 256, GSM_BYTES>>>(venue_emb, rows);
    geo_main_kernel<<<B / 2, 256>>>(batch_u, batch_v, batch_history,
                                    user_emb, venue_emb, a, out);
}